// round 14
// baseline (speedup 1.0000x reference)
#include <cuda_runtime.h>
#include <math.h>

#define N_NODES 1024
#define N_EDGES 16384
#define D_IN    128
#define ED      16
#define KTOP    8
#define NBLK    296
#define NT      256
#define LCAP    64
#define UCAP    64
#define UTH     0.97f

// ---------------- scratch (device globals) ----------------------------------
__device__ int   g_rowcnt[N_NODES];          // zero at load; restored by P3 each run
__device__ int   g_rowdst[N_NODES * LCAP];
__device__ int   g_rowe[N_NODES * LCAP];
__device__ float g_xwnode[N_NODES];
__device__ float g_xwnb[N_NODES];
__device__ float g_eval[N_EDGES];
__device__ int   g_topi[N_NODES * KTOP];
__device__ int   g_eid[N_NODES * KTOP];
__device__ float g_dn1[N_NODES * 2 * D_IN];  // interleaved den/num, conv1
__device__ float g_dn2[N_NODES * 2 * 64];    // interleaved den/num, conv2
__device__ float g_h1[N_NODES * 64];

__device__ unsigned g_count = 0;
__device__ unsigned g_gen = 0;

// ---------------- helpers ----------------------------------------------------
__device__ __forceinline__ void grid_sync(unsigned target) {
    __syncthreads();
    if (threadIdx.x == 0) {
        __threadfence();
        unsigned arrived = atomicAdd(&g_count, 1u);
        if (arrived == NBLK - 1) {
            g_count = 0;
            __threadfence();
            atomicAdd(&g_gen, 1u);
        } else {
            while (*((volatile unsigned*)&g_gen) < target) __nanosleep(32);
        }
        __threadfence();
    }
    __syncthreads();
}

#define QBAR(q) asm volatile("bar.sync %0, 64;" :: "r"((q) + 1) : "memory")

__device__ __forceinline__ void red_add_v4(float* addr, float a, float b, float c, float d) {
    asm volatile("red.global.add.v4.f32 [%0], {%1, %2, %3, %4};"
                 :: "l"(addr), "f"(a), "f"(b), "f"(c), "f"(d) : "memory");
}
__device__ __forceinline__ void red_add_v2(float* addr, float a, float b) {
    asm volatile("red.global.add.v2.f32 [%0], {%1, %2};"
                 :: "l"(addr), "f"(a), "f"(b) : "memory");
}

__device__ __forceinline__ unsigned long long packkey(float v, int j) {
    unsigned u = __float_as_uint(v);
    u = (u & 0x80000000u) ? ~u : (u | 0x80000000u);
    return ((unsigned long long)u << 32) | (unsigned)(1023 - j);
}
__device__ __forceinline__ unsigned long long packu(float u, int j) {
    return ((unsigned long long)__float_as_uint(u) << 32) | (unsigned)(1023 - j);
}
__device__ __forceinline__ unsigned long long wmax64(unsigned long long k) {
#pragma unroll
    for (int o = 16; o > 0; o >>= 1) {
        unsigned long long k2 = __shfl_xor_sync(0xffffffffu, k, o);
        if (k2 > k) k = k2;
    }
    return k;
}

// ---------------- shared memory union ----------------------------------------
struct alignas(16) TK {
    int dstl[LCAP]; int el[LCAP];
    float cv[LCAP];
    int   cj[LCAP + UCAP];
    int   ce[LCAP];
    unsigned msk[32];
    float attr[KTOP][ED];
    float zadd;
    int cnt, pcnt, ucnt;
    int topi8[KTOP]; int eid8[KTOP];
};
union SMem {
    TK tk[4];
    struct { float s0[4][128]; float h1s[4][256]; float hh[4][64];
             float a2[4][KTOP][ED]; int sd[4][KTOP]; int se[4][KTOP]; } c1;
    struct { float s0[4][64]; float h1s[4][128]; float h2s[4][64]; } c2;
};

// ---------------- the one kernel ----------------------------------------------
__global__ void __launch_bounds__(NT, 2)
gumbel_gcn_all(const float* __restrict__ x,
               const float* __restrict__ edge_attr,
               const float* __restrict__ gumbel,
               const float* __restrict__ mlp_w,
               const float* __restrict__ mlp_b,
               const float* __restrict__ c1_we, const float* __restrict__ c1_be,
               const float* __restrict__ c1_w1, const float* __restrict__ c1_b1,
               const float* __restrict__ c1_w2, const float* __restrict__ c1_b2,
               const float* __restrict__ c2_we, const float* __restrict__ c2_be,
               const float* __restrict__ c2_w1, const float* __restrict__ c2_b1,
               const float* __restrict__ c2_w2, const float* __restrict__ c2_b2,
               const float* __restrict__ fcw, const float* __restrict__ fcb,
               const int* __restrict__ ei, const int* __restrict__ mask,
               float* __restrict__ out) {
    __shared__ SMem sm;
    const int tid = threadIdx.x;
    const int bid = blockIdx.x;
    const int gtid = bid * NT + tid;
    const int lane = tid & 31;
    const int qid  = tid >> 6;        // 0..3
    const int qtid = tid & 63;
    const int qw   = (tid >> 5) & 1;
    const int i = bid * 4 + qid;      // row handled in P3 (valid when bid < 256)

    unsigned base = 0;
    if (tid == 0) base = *((volatile unsigned*)&g_gen);

    // ---- prefetch gumbel row (input-only; overlaps P1 + barrier) --------------
    float4 u0, u1, u2, u3;
    if (bid < N_NODES / 4) {
        const float4* grow4 = (const float4*)(gumbel + (size_t)i * N_NODES);
        u0 = grow4[qtid];
        u1 = grow4[64 + qtid];
        u2 = grow4[128 + qtid];
        u3 = grow4[192 + qtid];
    }

    // ===== P1: block-partitioned: edges | node dots | zeroing ==================
    if (bid < 64) {
        int e = gtid;
        float acc = 0.f;
        const float4* ea = (const float4*)(edge_attr + e * ED);
#pragma unroll
        for (int q = 0; q < 4; q++) {
            float4 v = ea[q];
            acc += v.x * mlp_w[2 * D_IN + q * 4]
                 + v.y * mlp_w[2 * D_IN + q * 4 + 1]
                 + v.z * mlp_w[2 * D_IN + q * 4 + 2]
                 + v.w * mlp_w[2 * D_IN + q * 4 + 3];
        }
        g_eval[e] = acc;
        int s = ei[e];
        int d = ei[N_EDGES + e];
        int p = atomicAdd(&g_rowcnt[s], 1);
        if (p < LCAP) {
            __stcg(&g_rowdst[s * LCAP + p], d);
            __stcg(&g_rowe[s * LCAP + p], e);
        }
    } else if (bid < 192) {
        int nid = ((bid - 64) * NT + tid) >> 5;
        float p1 = 0.f, p2 = 0.f;
#pragma unroll
        for (int q = 0; q < 4; q++) {
            float xv = x[nid * D_IN + q * 32 + lane];
            p1 += xv * mlp_w[q * 32 + lane];
            p2 += xv * mlp_w[D_IN + q * 32 + lane];
        }
#pragma unroll
        for (int o = 16; o > 0; o >>= 1) {
            p1 += __shfl_down_sync(0xffffffffu, p1, o);
            p2 += __shfl_down_sync(0xffffffffu, p2, o);
        }
        if (lane == 0) { g_xwnode[nid] = p1 + mlp_b[0]; g_xwnb[nid] = p2; }
    } else {
        int zt = (bid - 192) * NT + tid;
        const float4 z4 = make_float4(0.f, 0.f, 0.f, 0.f);
        for (int idx = zt; idx < (N_NODES * 2 * D_IN) / 4; idx += 104 * NT)
            __stcg(((float4*)g_dn1) + idx, z4);
        for (int idx = zt; idx < (N_NODES * 2 * 64) / 4; idx += 104 * NT)
            __stcg(((float4*)g_dn2) + idx, z4);
    }
    grid_sync(base + 1);

    // ===== P3: topk (4 rows/block, 64 threads each, per-quarter barriers) ======
    if (bid < N_NODES / 4) {
        TK& tk = sm.tk[qid];

        int dreg = __ldcg(&g_rowdst[i * LCAP + qtid]);
        int ereg = __ldcg(&g_rowe[i * LCAP + qtid]);

        if (qtid == 0) {
            tk.pcnt = 0; tk.ucnt = 0;
            int c = __ldcg(&g_rowcnt[i]);
            __stcg(&g_rowcnt[i], 0);      // restore zero for next run
            tk.cnt = c < LCAP ? c : LCAP;
        }
        if (qtid < 32) tk.msk[qtid] = 0u;
        tk.dstl[qtid] = dreg;
        tk.el[qtid]   = ereg;
        QBAR(qid);
        int cnt = tk.cnt;

        // dedupe + primary push (last-edge-wins score, first-edge eid)
        if (qtid < cnt) {
            int d = tk.dstl[qtid], e = tk.el[qtid];
            int maxe = e, mine = e;
            for (int q = 0; q < cnt; q++) {
                if (tk.dstl[q] == d) {
                    int eq = tk.el[q];
                    maxe = max(maxe, eq); mine = min(mine, eq);
                }
            }
            atomicOr(&tk.msk[d >> 5], 1u << (d & 31));
            if (e == maxe) {
                float s = g_xwnode[i] + g_xwnb[d] + g_eval[e];
                int p = atomicAdd(&tk.pcnt, 1);
                tk.cv[p] = s; tk.cj[p] = d; tk.ce[p] = mine;
            }
        }
        QBAR(qid);
        int pcnt = tk.pcnt;

        // threshold scan on prefetched gumbel values
        {
#pragma unroll
            for (int r = 0; r < 4; r++) {
                float4 uv = (r == 0) ? u0 : (r == 1) ? u1 : (r == 2) ? u2 : u3;
                int j0 = r * 256 + qtid * 4;
                unsigned wb = tk.msk[j0 >> 5];
                int sh = j0 & 31;
                if (uv.x > UTH && !((wb >> (sh + 0)) & 1u)) { int p = atomicAdd(&tk.ucnt, 1); if (p < UCAP) tk.cj[LCAP + p] = j0; }
                if (uv.y > UTH && !((wb >> (sh + 1)) & 1u)) { int p = atomicAdd(&tk.ucnt, 1); if (p < UCAP) tk.cj[LCAP + p] = j0 + 1; }
                if (uv.z > UTH && !((wb >> (sh + 2)) & 1u)) { int p = atomicAdd(&tk.ucnt, 1); if (p < UCAP) tk.cj[LCAP + p] = j0 + 2; }
                if (uv.w > UTH && !((wb >> (sh + 3)) & 1u)) { int p = atomicAdd(&tk.ucnt, 1); if (p < UCAP) tk.cj[LCAP + p] = j0 + 3; }
            }
        }

        // sparse softmax over primaries (warp 0 of quarter)
        if (qw == 0) {
            float lm = -3.4e38f;
            for (int p = lane; p < pcnt; p += 32) lm = fmaxf(lm, tk.cv[p]);
#pragma unroll
            for (int o = 16; o > 0; o >>= 1) lm = fmaxf(lm, __shfl_xor_sync(0xffffffffu, lm, o));
            float ls = 0.f;
            for (int p = lane; p < pcnt; p += 32) ls += expf(tk.cv[p] - lm);
#pragma unroll
            for (int o = 16; o > 0; o >>= 1) ls += __shfl_xor_sync(0xffffffffu, ls, o);
            float inv = 1.f / ls;
            for (int p = lane; p < pcnt; p += 32)
                tk.cv[p] = expf(tk.cv[p] - lm) * inv;
            if (lane == 0) tk.zadd = (pcnt == 0) ? (1.f / 1024.f) : 0.f;
        }
        QBAR(qid);
        float zadd = tk.zadd;

        // rare exact fallback
        if (qw == 0 && (tk.ucnt < 8 || tk.ucnt > UCAP)) {
            if (lane == 0) tk.ucnt = 8;
            const float* grow = gumbel + (size_t)i * N_NODES;
#pragma unroll 1
            for (int r = 0; r < 8; r++) {
                unsigned long long best = 0ull;
#pragma unroll 1
                for (int q = 0; q < 32; q++) {
                    int j = q * 32 + lane;
                    if (!((tk.msk[j >> 5] >> (j & 31)) & 1u)) {
                        unsigned long long kx = packu(grow[j], j);
                        if (kx > best) best = kx;
                    }
                }
                unsigned long long m = wmax64(best);
                if (lane == 0) {
                    int j = 1023 - (int)(m & 0xFFFFFFFFull);
                    tk.cj[LCAP + r] = j;
                    tk.msk[j >> 5] |= 1u << (j & 31);
                }
                __syncwarp();
            }
        }
        QBAR(qid);

        // exact evaluation of candidates, top-8 with index tie-break
        if (qw == 0) {
            int ueff = tk.ucnt < UCAP ? tk.ucnt : UCAP;
            unsigned long long kk[4];
            int ee[4]; int jj[4];
#pragma unroll
            for (int q = 0; q < 4; q++) { kk[q] = 0ull; ee[q] = 0; jj[q] = 0; }
#pragma unroll
            for (int q = 0; q < 2; q++) {        // primaries
                int p = lane + q * 32;
                if (p < pcnt) {
                    int j = tk.cj[p];
                    float u = gumbel[(size_t)i * N_NODES + j];
                    float g = -logf(-logf(u + 1e-20f) + 1e-20f);
                    kk[q] = packkey(tk.cv[p] + zadd + g, j);
                    ee[q] = tk.ce[p]; jj[q] = j;
                }
            }
#pragma unroll
            for (int q = 0; q < 2; q++) {        // uniform candidates (z = 0)
                int p = lane + q * 32;
                if (p < ueff) {
                    int j = tk.cj[LCAP + p];
                    float u = gumbel[(size_t)i * N_NODES + j];
                    float g = -logf(-logf(u + 1e-20f) + 1e-20f);
                    kk[2 + q] = packkey(zadd + g, j);
                    ee[2 + q] = 0; jj[2 + q] = j;
                }
            }
#pragma unroll
            for (int r = 0; r < 8; r++) {
                unsigned long long best = kk[0];
#pragma unroll
                for (int q = 1; q < 4; q++) if (kk[q] > best) best = kk[q];
                unsigned long long m = wmax64(best);
#pragma unroll
                for (int q = 0; q < 4; q++) {
                    if (kk[q] == m) {
                        tk.topi8[r] = jj[q];
                        tk.eid8[r]  = ee[q];
                        g_topi[i * KTOP + r] = jj[q];
                        g_eid[i * KTOP + r]  = ee[q];
                        kk[q] = 0ull;
                    }
                }
            }
        }
        QBAR(qid);

        // conv1 edge attrs (8 selected edges)
        {
            int k0 = qtid >> 4, c0 = qtid & 15;
            tk.attr[k0][c0] = edge_attr[tk.eid8[k0] * ED + c0];
            int idx1 = qtid + 64;
            int k1 = idx1 >> 4, c1 = idx1 & 15;
            tk.attr[k1][c1] = edge_attr[tk.eid8[k1] * ED + c1];
        }
        QBAR(qid);
        {
            int f0 = qtid * 2;                       // features f0, f0+1
            float2 xv = *(const float2*)&x[i * D_IN + f0];
            float2 be = *(const float2*)&c1_be[f0];
            float2 wr[ED];
#pragma unroll
            for (int c = 0; c < ED; c++) wr[c] = *(const float2*)&c1_we[c * D_IN + f0];
#pragma unroll
            for (int kq = 0; kq < KTOP; kq++) {
                float ep0 = be.x, ep1 = be.y;
#pragma unroll
                for (int c = 0; c < ED; c++) {
                    float av = tk.attr[kq][c];
                    ep0 += av * wr[c].x;
                    ep1 += av * wr[c].y;
                }
                float m0 = fmaxf(xv.x + ep0, 0.f) + 1e-7f;
                float m1 = fmaxf(xv.y + ep1, 0.f) + 1e-7f;
                float w0 = __expf(m0);
                float w1 = __expf(m1);
                int dst = tk.topi8[kq];
                red_add_v4(&g_dn1[dst * 2 * D_IN + f0 * 2], w0, w0 * m0, w1, w1 * m1);
            }
        }
    }
    grid_sync(base + 2);

    // ===== P5: conv1 node MLP (4 nodes/block) + conv2 edge msgs ================
    if (bid < N_NODES / 4) {
        int nb = bid * 4;
        for (int idx = tid; idx < 4 * 128; idx += NT) {
            int n = idx >> 7, f = idx & 127;
            float2 dn = *(const float2*)&g_dn1[(nb + n) * 2 * D_IN + f * 2];
            sm.c1.s0[n][f] = ((dn.x > 0.f) ? dn.y / dn.x : 0.f) + x[(nb + n) * 128 + f];
        }
        __syncthreads();
        {
            float acc[4];
            float bb = c1_b1[tid];
#pragma unroll
            for (int n = 0; n < 4; n++) acc[n] = bb;
            for (int c = 0; c < 128; c += 4) {
                float w0 = c1_w1[(c + 0) * 256 + tid];
                float w1 = c1_w1[(c + 1) * 256 + tid];
                float w2 = c1_w1[(c + 2) * 256 + tid];
                float w3 = c1_w1[(c + 3) * 256 + tid];
#pragma unroll
                for (int n = 0; n < 4; n++) {
                    float4 s4 = *(const float4*)&sm.c1.s0[n][c];
                    acc[n] += s4.x * w0 + s4.y * w1 + s4.z * w2 + s4.w * w3;
                }
            }
#pragma unroll
            for (int n = 0; n < 4; n++) sm.c1.h1s[n][tid] = fmaxf(acc[n], 0.f);
        }
        __syncthreads();
        {
            int o = tid & 63, n = tid >> 6;
            float a = c1_b2[o];
            for (int c = 0; c < 256; c += 4) {
                float4 h4 = *(const float4*)&sm.c1.h1s[n][c];
                a += h4.x * c1_w2[(c + 0) * 64 + o]
                   + h4.y * c1_w2[(c + 1) * 64 + o]
                   + h4.z * c1_w2[(c + 2) * 64 + o]
                   + h4.w * c1_w2[(c + 3) * 64 + o];
            }
            float hv = fmaxf(a, 0.f);  // post-conv relu
            g_h1[(nb + n) * 64 + o] = hv;
            sm.c1.hh[n][o] = hv;
            if (o < KTOP) {
                sm.c1.sd[n][o] = g_topi[(nb + n) * KTOP + o];
                sm.c1.se[n][o] = g_eid[(nb + n) * KTOP + o];
            }
        }
        __syncthreads();
        for (int idx = tid; idx < 4 * KTOP * ED; idx += NT) {
            int n = idx >> 7, r = idx & 127;
            int kq = r >> 4, c = r & 15;
            sm.c1.a2[n][kq][c] = edge_attr[sm.c1.se[n][kq] * ED + c];
        }
        __syncthreads();
        {
            int f = tid & 63, n = tid >> 6;
            float xv = sm.c1.hh[n][f];
            float beh = c2_be[f];
            float wr[ED];
#pragma unroll
            for (int c = 0; c < ED; c++) wr[c] = c2_we[c * 64 + f];
#pragma unroll
            for (int kq = 0; kq < KTOP; kq++) {
                float ep = beh;
#pragma unroll
                for (int c = 0; c < ED; c++) ep += sm.c1.a2[n][kq][c] * wr[c];
                float m = fmaxf(xv + ep, 0.f) + 1e-7f;
                float wgt = __expf(m);
                int dst = sm.c1.sd[n][kq];
                red_add_v2(&g_dn2[dst * 128 + f * 2], wgt, wgt * m);
            }
        }
    }
    grid_sync(base + 3);

    // ===== P7: conv2 node MLP + final FC + mask =================================
    if (bid < N_NODES / 4) {
        int nb = bid * 4;
        for (int idx = tid; idx < 4 * 64; idx += NT) {
            int n = idx >> 6, f = idx & 63;
            float2 dn = *(const float2*)&g_dn2[(nb + n) * 128 + f * 2];
            sm.c2.s0[n][f] = ((dn.x > 0.f) ? dn.y / dn.x : 0.f) + g_h1[(nb + n) * 64 + f];
        }
        __syncthreads();
        {
            int h = tid & 127, n2 = (tid >> 7) * 2;
            float a0 = c2_b1[h], a1 = a0;
            for (int c = 0; c < 64; c += 4) {
                float w0 = c2_w1[(c + 0) * 128 + h];
                float w1 = c2_w1[(c + 1) * 128 + h];
                float w2 = c2_w1[(c + 2) * 128 + h];
                float w3 = c2_w1[(c + 3) * 128 + h];
                float4 s4a = *(const float4*)&sm.c2.s0[n2][c];
                float4 s4b = *(const float4*)&sm.c2.s0[n2 + 1][c];
                a0 += s4a.x * w0 + s4a.y * w1 + s4a.z * w2 + s4a.w * w3;
                a1 += s4b.x * w0 + s4b.y * w1 + s4b.z * w2 + s4b.w * w3;
            }
            sm.c2.h1s[n2][h]     = fmaxf(a0, 0.f);
            sm.c2.h1s[n2 + 1][h] = fmaxf(a1, 0.f);
        }
        __syncthreads();
        {
            int o = tid & 63, n = tid >> 6;
            float a = c2_b2[o];
            for (int c = 0; c < 128; c += 4) {
                float4 h4 = *(const float4*)&sm.c2.h1s[n][c];
                a += h4.x * c2_w2[(c + 0) * 64 + o]
                   + h4.y * c2_w2[(c + 1) * 64 + o]
                   + h4.z * c2_w2[(c + 2) * 64 + o]
                   + h4.w * c2_w2[(c + 3) * 64 + o];
            }
            sm.c2.h2s[n][o] = fmaxf(a, 0.f);  // post-conv relu
        }
        __syncthreads();
        for (int idx = tid; idx < 4 * 40; idx += NT) {
            int n = idx / 40, o2 = idx % 40;
            float a2 = fcb[o2];
#pragma unroll 16
            for (int c = 0; c < 64; c++) a2 += sm.c2.h2s[n][c] * fcw[c * 40 + o2];
            out[(nb + n) * 40 + o2] = (mask[nb + n] != 0) ? a2 : 0.f;
        }
    }
}

// ---------------- launch ------------------------------------------------------
extern "C" void kernel_launch(void* const* d_in, const int* in_sizes, int n_in,
                              void* d_out, int out_size) {
    gumbel_gcn_all<<<NBLK, NT>>>(
        (const float*)d_in[0],  (const float*)d_in[1],  (const float*)d_in[2],
        (const float*)d_in[3],  (const float*)d_in[4],
        (const float*)d_in[5],  (const float*)d_in[6],
        (const float*)d_in[7],  (const float*)d_in[8],
        (const float*)d_in[9],  (const float*)d_in[10],
        (const float*)d_in[11], (const float*)d_in[12],
        (const float*)d_in[13], (const float*)d_in[14],
        (const float*)d_in[15], (const float*)d_in[16],
        (const float*)d_in[17], (const float*)d_in[18],
        (const int*)d_in[20],   (const int*)d_in[21],
        (float*)d_out);
}

// round 15
// speedup vs baseline: 1.0109x; 1.0109x over previous
#include <cuda_runtime.h>
#include <math.h>

#define N_NODES 1024
#define N_EDGES 16384
#define D_IN    128
#define ED      16
#define KTOP    8
#define NBLK    296
#define NT      256
#define LCAP    64
#define UCAP    64
#define UTH     0.97f

// ---------------- scratch (device globals) ----------------------------------
__device__ int   g_rowcnt[N_NODES];          // zero at load; restored by P3 each run
__device__ int   g_rowdst[N_NODES * LCAP];
__device__ int   g_rowe[N_NODES * LCAP];
__device__ float g_xwnode[N_NODES];
__device__ float g_xwnb[N_NODES];
__device__ float g_eval[N_EDGES];
__device__ int   g_topi[N_NODES * KTOP];
__device__ int   g_eid[N_NODES * KTOP];
__device__ float g_dn1[N_NODES * 2 * D_IN];  // interleaved den/num, conv1
__device__ float g_dn2[N_NODES * 2 * 64];    // interleaved den/num, conv2
__device__ float g_h1[N_NODES * 64];

__device__ unsigned g_count = 0;
__device__ unsigned g_gen = 0;

// ---------------- helpers ----------------------------------------------------
__device__ __forceinline__ void grid_sync(unsigned target) {
    __syncthreads();
    if (threadIdx.x == 0) {
        __threadfence();
        unsigned arrived = atomicAdd(&g_count, 1u);
        if (arrived == NBLK - 1) {
            g_count = 0;
            __threadfence();
            atomicAdd(&g_gen, 1u);
        } else {
            while (*((volatile unsigned*)&g_gen) < target) __nanosleep(32);
        }
        __threadfence();
    }
    __syncthreads();
}

#define QBAR(q) asm volatile("bar.sync %0, 64;" :: "r"((q) + 1) : "memory")

__device__ __forceinline__ void red_add_v4(float* addr, float a, float b, float c, float d) {
    asm volatile("red.global.add.v4.f32 [%0], {%1, %2, %3, %4};"
                 :: "l"(addr), "f"(a), "f"(b), "f"(c), "f"(d) : "memory");
}
__device__ __forceinline__ void red_add_v2(float* addr, float a, float b) {
    asm volatile("red.global.add.v2.f32 [%0], {%1, %2};"
                 :: "l"(addr), "f"(a), "f"(b) : "memory");
}

__device__ __forceinline__ unsigned long long packkey(float v, int j) {
    unsigned u = __float_as_uint(v);
    u = (u & 0x80000000u) ? ~u : (u | 0x80000000u);
    return ((unsigned long long)u << 32) | (unsigned)(1023 - j);
}
__device__ __forceinline__ unsigned long long packu(float u, int j) {
    return ((unsigned long long)__float_as_uint(u) << 32) | (unsigned)(1023 - j);
}
__device__ __forceinline__ unsigned long long wmax64(unsigned long long k) {
#pragma unroll
    for (int o = 16; o > 0; o >>= 1) {
        unsigned long long k2 = __shfl_xor_sync(0xffffffffu, k, o);
        if (k2 > k) k = k2;
    }
    return k;
}

// ---------------- shared memory union ----------------------------------------
struct alignas(16) TK {
    int dstl[LCAP]; int el[LCAP];
    float cv[LCAP];
    int   cj[LCAP + UCAP];
    int   ce[LCAP];
    unsigned msk[32];
    float attr[KTOP][ED];
    float zadd;
    int cnt, pcnt, ucnt;
    int topi8[KTOP]; int eid8[KTOP];
};
union SMem {
    TK tk[4];
    struct { float s0[4][128]; float h1s[4][256]; float hh[4][64];
             float a2[4][KTOP][ED]; int sd[4][KTOP]; int se[4][KTOP]; } c1;
    struct { float s0[4][64]; float h1s[4][128]; float h2s[4][64]; } c2;
};

// ---------------- the one kernel ----------------------------------------------
__global__ void __launch_bounds__(NT, 2)
gumbel_gcn_all(const float* __restrict__ x,
               const float* __restrict__ edge_attr,
               const float* __restrict__ gumbel,
               const float* __restrict__ mlp_w,
               const float* __restrict__ mlp_b,
               const float* __restrict__ c1_we, const float* __restrict__ c1_be,
               const float* __restrict__ c1_w1, const float* __restrict__ c1_b1,
               const float* __restrict__ c1_w2, const float* __restrict__ c1_b2,
               const float* __restrict__ c2_we, const float* __restrict__ c2_be,
               const float* __restrict__ c2_w1, const float* __restrict__ c2_b1,
               const float* __restrict__ c2_w2, const float* __restrict__ c2_b2,
               const float* __restrict__ fcw, const float* __restrict__ fcb,
               const int* __restrict__ ei, const int* __restrict__ mask,
               float* __restrict__ out) {
    __shared__ SMem sm;
    const int tid = threadIdx.x;
    const int bid = blockIdx.x;
    const int gtid = bid * NT + tid;
    const int lane = tid & 31;
    const int qid  = tid >> 6;        // 0..3
    const int qtid = tid & 63;
    const int qw   = (tid >> 5) & 1;
    const int i = qid * NBLK + bid;   // P3 row (spread over all 296 blocks)
    const bool rowact = (i < N_NODES);

    unsigned base = 0;
    if (tid == 0) base = *((volatile unsigned*)&g_gen);

    // ---- prefetch gumbel row (input-only; overlaps P1 + barrier) --------------
    float4 u0, u1, u2, u3;
    if (rowact) {
        const float4* grow4 = (const float4*)(gumbel + (size_t)i * N_NODES);
        u0 = grow4[qtid];
        u1 = grow4[64 + qtid];
        u2 = grow4[128 + qtid];
        u3 = grow4[192 + qtid];
    }

    // ===== P1: block-partitioned: edges | node dots | zeroing ==================
    if (bid < 64) {
        int e = gtid;
        float acc = 0.f;
        const float4* ea = (const float4*)(edge_attr + e * ED);
#pragma unroll
        for (int q = 0; q < 4; q++) {
            float4 v = ea[q];
            acc += v.x * mlp_w[2 * D_IN + q * 4]
                 + v.y * mlp_w[2 * D_IN + q * 4 + 1]
                 + v.z * mlp_w[2 * D_IN + q * 4 + 2]
                 + v.w * mlp_w[2 * D_IN + q * 4 + 3];
        }
        g_eval[e] = acc;
        int s = ei[e];
        int d = ei[N_EDGES + e];
        int p = atomicAdd(&g_rowcnt[s], 1);
        if (p < LCAP) {
            __stcg(&g_rowdst[s * LCAP + p], d);
            __stcg(&g_rowe[s * LCAP + p], e);
        }
    } else if (bid < 192) {
        int nid = ((bid - 64) * NT + tid) >> 5;
        float p1 = 0.f, p2 = 0.f;
#pragma unroll
        for (int q = 0; q < 4; q++) {
            float xv = x[nid * D_IN + q * 32 + lane];
            p1 += xv * mlp_w[q * 32 + lane];
            p2 += xv * mlp_w[D_IN + q * 32 + lane];
        }
#pragma unroll
        for (int o = 16; o > 0; o >>= 1) {
            p1 += __shfl_down_sync(0xffffffffu, p1, o);
            p2 += __shfl_down_sync(0xffffffffu, p2, o);
        }
        if (lane == 0) { g_xwnode[nid] = p1 + mlp_b[0]; g_xwnb[nid] = p2; }
    } else {
        int zt = (bid - 192) * NT + tid;
        const float4 z4 = make_float4(0.f, 0.f, 0.f, 0.f);
        for (int idx = zt; idx < (N_NODES * 2 * D_IN) / 4; idx += 104 * NT)
            __stcg(((float4*)g_dn1) + idx, z4);
        for (int idx = zt; idx < (N_NODES * 2 * 64) / 4; idx += 104 * NT)
            __stcg(((float4*)g_dn2) + idx, z4);
    }
    grid_sync(base + 1);

    // ===== P3: topk (rows spread over all blocks, 64 threads each) =============
    if (rowact) {
        TK& tk = sm.tk[qid];

        int dreg = __ldcg(&g_rowdst[i * LCAP + qtid]);
        int ereg = __ldcg(&g_rowe[i * LCAP + qtid]);

        if (qtid == 0) {
            tk.pcnt = 0; tk.ucnt = 0;
            int c = __ldcg(&g_rowcnt[i]);
            __stcg(&g_rowcnt[i], 0);      // restore zero for next run
            tk.cnt = c < LCAP ? c : LCAP;
        }
        if (qtid < 32) tk.msk[qtid] = 0u;
        tk.dstl[qtid] = dreg;
        tk.el[qtid]   = ereg;
        QBAR(qid);
        int cnt = tk.cnt;

        // dedupe + primary push (last-edge-wins score, first-edge eid)
        if (qtid < cnt) {
            int d = tk.dstl[qtid], e = tk.el[qtid];
            int maxe = e, mine = e;
            for (int q = 0; q < cnt; q++) {
                if (tk.dstl[q] == d) {
                    int eq = tk.el[q];
                    maxe = max(maxe, eq); mine = min(mine, eq);
                }
            }
            atomicOr(&tk.msk[d >> 5], 1u << (d & 31));
            if (e == maxe) {
                float s = g_xwnode[i] + g_xwnb[d] + g_eval[e];
                int p = atomicAdd(&tk.pcnt, 1);
                tk.cv[p] = s; tk.cj[p] = d; tk.ce[p] = mine;
            }
        }
        QBAR(qid);
        int pcnt = tk.pcnt;

        // threshold scan on prefetched gumbel values
        {
#pragma unroll
            for (int r = 0; r < 4; r++) {
                float4 uv = (r == 0) ? u0 : (r == 1) ? u1 : (r == 2) ? u2 : u3;
                int j0 = r * 256 + qtid * 4;
                unsigned wb = tk.msk[j0 >> 5];
                int sh = j0 & 31;
                if (uv.x > UTH && !((wb >> (sh + 0)) & 1u)) { int p = atomicAdd(&tk.ucnt, 1); if (p < UCAP) tk.cj[LCAP + p] = j0; }
                if (uv.y > UTH && !((wb >> (sh + 1)) & 1u)) { int p = atomicAdd(&tk.ucnt, 1); if (p < UCAP) tk.cj[LCAP + p] = j0 + 1; }
                if (uv.z > UTH && !((wb >> (sh + 2)) & 1u)) { int p = atomicAdd(&tk.ucnt, 1); if (p < UCAP) tk.cj[LCAP + p] = j0 + 2; }
                if (uv.w > UTH && !((wb >> (sh + 3)) & 1u)) { int p = atomicAdd(&tk.ucnt, 1); if (p < UCAP) tk.cj[LCAP + p] = j0 + 3; }
            }
        }

        // sparse softmax over primaries (warp 0 of quarter)
        if (qw == 0) {
            float lm = -3.4e38f;
            for (int p = lane; p < pcnt; p += 32) lm = fmaxf(lm, tk.cv[p]);
#pragma unroll
            for (int o = 16; o > 0; o >>= 1) lm = fmaxf(lm, __shfl_xor_sync(0xffffffffu, lm, o));
            float ls = 0.f;
            for (int p = lane; p < pcnt; p += 32) ls += expf(tk.cv[p] - lm);
#pragma unroll
            for (int o = 16; o > 0; o >>= 1) ls += __shfl_xor_sync(0xffffffffu, ls, o);
            float inv = 1.f / ls;
            for (int p = lane; p < pcnt; p += 32)
                tk.cv[p] = expf(tk.cv[p] - lm) * inv;
            if (lane == 0) tk.zadd = (pcnt == 0) ? (1.f / 1024.f) : 0.f;
        }
        QBAR(qid);
        float zadd = tk.zadd;

        // rare exact fallback
        if (qw == 0 && (tk.ucnt < 8 || tk.ucnt > UCAP)) {
            if (lane == 0) tk.ucnt = 8;
            const float* grow = gumbel + (size_t)i * N_NODES;
#pragma unroll 1
            for (int r = 0; r < 8; r++) {
                unsigned long long best = 0ull;
#pragma unroll 1
                for (int q = 0; q < 32; q++) {
                    int j = q * 32 + lane;
                    if (!((tk.msk[j >> 5] >> (j & 31)) & 1u)) {
                        unsigned long long kx = packu(grow[j], j);
                        if (kx > best) best = kx;
                    }
                }
                unsigned long long m = wmax64(best);
                if (lane == 0) {
                    int j = 1023 - (int)(m & 0xFFFFFFFFull);
                    tk.cj[LCAP + r] = j;
                    tk.msk[j >> 5] |= 1u << (j & 31);
                }
                __syncwarp();
            }
        }
        QBAR(qid);

        // exact evaluation of candidates, top-8 with index tie-break
        if (qw == 0) {
            int ueff = tk.ucnt < UCAP ? tk.ucnt : UCAP;
            unsigned long long kk[4];
            int ee[4]; int jj[4];
#pragma unroll
            for (int q = 0; q < 4; q++) { kk[q] = 0ull; ee[q] = 0; jj[q] = 0; }
#pragma unroll
            for (int q = 0; q < 2; q++) {        // primaries
                int p = lane + q * 32;
                if (p < pcnt) {
                    int j = tk.cj[p];
                    float u = gumbel[(size_t)i * N_NODES + j];
                    float g = -logf(-logf(u + 1e-20f) + 1e-20f);
                    kk[q] = packkey(tk.cv[p] + zadd + g, j);
                    ee[q] = tk.ce[p]; jj[q] = j;
                }
            }
#pragma unroll
            for (int q = 0; q < 2; q++) {        // uniform candidates (z = 0)
                int p = lane + q * 32;
                if (p < ueff) {
                    int j = tk.cj[LCAP + p];
                    float u = gumbel[(size_t)i * N_NODES + j];
                    float g = -logf(-logf(u + 1e-20f) + 1e-20f);
                    kk[2 + q] = packkey(zadd + g, j);
                    ee[2 + q] = 0; jj[2 + q] = j;
                }
            }
#pragma unroll
            for (int r = 0; r < 8; r++) {
                unsigned long long best = kk[0];
#pragma unroll
                for (int q = 1; q < 4; q++) if (kk[q] > best) best = kk[q];
                unsigned long long m = wmax64(best);
#pragma unroll
                for (int q = 0; q < 4; q++) {
                    if (kk[q] == m) {
                        tk.topi8[r] = jj[q];
                        tk.eid8[r]  = ee[q];
                        g_topi[i * KTOP + r] = jj[q];
                        g_eid[i * KTOP + r]  = ee[q];
                        kk[q] = 0ull;
                    }
                }
            }
        }
        QBAR(qid);

        // conv1 edge attrs (8 selected edges)
        {
            int k0 = qtid >> 4, c0 = qtid & 15;
            tk.attr[k0][c0] = edge_attr[tk.eid8[k0] * ED + c0];
            int idx1 = qtid + 64;
            int k1 = idx1 >> 4, c1 = idx1 & 15;
            tk.attr[k1][c1] = edge_attr[tk.eid8[k1] * ED + c1];
        }
        QBAR(qid);
        {
            int f0 = qtid * 2;                       // features f0, f0+1
            float2 xv = *(const float2*)&x[i * D_IN + f0];
            float2 be = *(const float2*)&c1_be[f0];
            float2 wr[ED];
#pragma unroll
            for (int c = 0; c < ED; c++) wr[c] = *(const float2*)&c1_we[c * D_IN + f0];
#pragma unroll
            for (int kq = 0; kq < KTOP; kq++) {
                float ep0 = be.x, ep1 = be.y;
#pragma unroll
                for (int c = 0; c < ED; c++) {
                    float av = tk.attr[kq][c];
                    ep0 += av * wr[c].x;
                    ep1 += av * wr[c].y;
                }
                float m0 = fmaxf(xv.x + ep0, 0.f) + 1e-7f;
                float m1 = fmaxf(xv.y + ep1, 0.f) + 1e-7f;
                float w0 = __expf(m0);
                float w1 = __expf(m1);
                int dst = tk.topi8[kq];
                red_add_v4(&g_dn1[dst * 2 * D_IN + f0 * 2], w0, w0 * m0, w1, w1 * m1);
            }
        }
    }
    grid_sync(base + 2);

    // ===== P5: conv1 node MLP (3-4 nodes/block over all 296) + conv2 edge msgs =
    {
        const int nb   = (bid * N_NODES) / NBLK;
        const int cntn = ((bid + 1) * N_NODES) / NBLK - nb;   // 3 or 4
        for (int idx = tid; idx < 4 * 128; idx += NT) {
            int n = idx >> 7, f = idx & 127;
            float v = 0.f;
            if (n < cntn) {
                float2 dn = *(const float2*)&g_dn1[(nb + n) * 2 * D_IN + f * 2];
                v = ((dn.x > 0.f) ? dn.y / dn.x : 0.f) + x[(nb + n) * 128 + f];
            }
            sm.c1.s0[n][f] = v;
        }
        __syncthreads();
        {
            float acc[4];
            float bb = c1_b1[tid];
#pragma unroll
            for (int n = 0; n < 4; n++) acc[n] = bb;
            for (int c = 0; c < 128; c++) {
                float wv = c1_w1[c * 256 + tid];
#pragma unroll
                for (int n = 0; n < 4; n++) acc[n] += sm.c1.s0[n][c] * wv;
            }
#pragma unroll
            for (int n = 0; n < 4; n++) sm.c1.h1s[n][tid] = fmaxf(acc[n], 0.f);
        }
        __syncthreads();
        {
            int o = tid & 63, n = tid >> 6;
            float a = c1_b2[o];
            for (int c = 0; c < 256; c++) a += sm.c1.h1s[n][c] * c1_w2[c * 64 + o];
            if (n < cntn) {
                float hv = fmaxf(a, 0.f);  // post-conv relu
                g_h1[(nb + n) * 64 + o] = hv;
                sm.c1.hh[n][o] = hv;
                if (o < KTOP) {
                    sm.c1.sd[n][o] = g_topi[(nb + n) * KTOP + o];
                    sm.c1.se[n][o] = g_eid[(nb + n) * KTOP + o];
                }
            }
        }
        __syncthreads();
        for (int idx = tid; idx < 4 * KTOP * ED; idx += NT) {
            int n = idx >> 7, r = idx & 127;
            if (n < cntn) {
                int kq = r >> 4, c = r & 15;
                sm.c1.a2[n][kq][c] = edge_attr[sm.c1.se[n][kq] * ED + c];
            }
        }
        __syncthreads();
        {
            int f = tid & 63, n = tid >> 6;
            if (n < cntn) {
                float xv = sm.c1.hh[n][f];
                float beh = c2_be[f];
                float wr[ED];
#pragma unroll
                for (int c = 0; c < ED; c++) wr[c] = c2_we[c * 64 + f];
#pragma unroll
                for (int kq = 0; kq < KTOP; kq++) {
                    float ep = beh;
#pragma unroll
                    for (int c = 0; c < ED; c++) ep += sm.c1.a2[n][kq][c] * wr[c];
                    float m = fmaxf(xv + ep, 0.f) + 1e-7f;
                    float wgt = __expf(m);
                    int dst = sm.c1.sd[n][kq];
                    red_add_v2(&g_dn2[dst * 128 + f * 2], wgt, wgt * m);
                }
            }
        }
    }
    grid_sync(base + 3);

    // ===== P7: conv2 node MLP + final FC + mask (3-4 nodes/block) ==============
    {
        const int nb   = (bid * N_NODES) / NBLK;
        const int cntn = ((bid + 1) * N_NODES) / NBLK - nb;
        for (int idx = tid; idx < 4 * 64; idx += NT) {
            int n = idx >> 6, f = idx & 63;
            float v = 0.f;
            if (n < cntn) {
                float2 dn = *(const float2*)&g_dn2[(nb + n) * 128 + f * 2];
                v = ((dn.x > 0.f) ? dn.y / dn.x : 0.f) + g_h1[(nb + n) * 64 + f];
            }
            sm.c2.s0[n][f] = v;
        }
        __syncthreads();
        {
            int h = tid & 127, n2 = (tid >> 7) * 2;
            float a0 = c2_b1[h], a1 = a0;
            for (int c = 0; c < 64; c++) {
                float wv = c2_w1[c * 128 + h];
                a0 += sm.c2.s0[n2][c] * wv;
                a1 += sm.c2.s0[n2 + 1][c] * wv;
            }
            sm.c2.h1s[n2][h]     = fmaxf(a0, 0.f);
            sm.c2.h1s[n2 + 1][h] = fmaxf(a1, 0.f);
        }
        __syncthreads();
        {
            int o = tid & 63, n = tid >> 6;
            float a = c2_b2[o];
            for (int c = 0; c < 128; c++) a += sm.c2.h1s[n][c] * c2_w2[c * 64 + o];
            sm.c2.h2s[n][o] = fmaxf(a, 0.f);  // post-conv relu (garbage if n>=cntn, unused)
        }
        __syncthreads();
        for (int idx = tid; idx < 4 * 40; idx += NT) {
            int n = idx / 40, o2 = idx % 40;
            if (n < cntn) {
                float a2 = fcb[o2];
#pragma unroll 16
                for (int c = 0; c < 64; c++) a2 += sm.c2.h2s[n][c] * fcw[c * 40 + o2];
                out[(nb + n) * 40 + o2] = (mask[nb + n] != 0) ? a2 : 0.f;
            }
        }
    }
}

// ---------------- launch ------------------------------------------------------
extern "C" void kernel_launch(void* const* d_in, const int* in_sizes, int n_in,
                              void* d_out, int out_size) {
    gumbel_gcn_all<<<NBLK, NT>>>(
        (const float*)d_in[0],  (const float*)d_in[1],  (const float*)d_in[2],
        (const float*)d_in[3],  (const float*)d_in[4],
        (const float*)d_in[5],  (const float*)d_in[6],
        (const float*)d_in[7],  (const float*)d_in[8],
        (const float*)d_in[9],  (const float*)d_in[10],
        (const float*)d_in[11], (const float*)d_in[12],
        (const float*)d_in[13], (const float*)d_in[14],
        (const float*)d_in[15], (const float*)d_in[16],
        (const float*)d_in[17], (const float*)d_in[18],
        (const int*)d_in[20],   (const int*)d_in[21],
        (float*)d_out);
}

// round 16
// speedup vs baseline: 1.1097x; 1.0977x over previous
#include <cuda_runtime.h>
#include <math.h>

#define N_NODES 1024
#define N_EDGES 16384
#define D_IN    128
#define ED      16
#define KTOP    8
#define NBLK    296
#define NT      256
#define LCAP    64
#define UCAP    64
#define UTH     0.97f

// ---------------- scratch (device globals) ----------------------------------
__device__ int   g_rowcnt[N_NODES];          // zero at load; restored by P3 each run
__device__ int   g_rowdst[N_NODES * LCAP];
__device__ int   g_rowe[N_NODES * LCAP];
__device__ float g_xwnode[N_NODES];
__device__ float g_xwnb[N_NODES];
__device__ float g_eval[N_EDGES];
__device__ int   g_topi[N_NODES * KTOP];
__device__ int   g_eid[N_NODES * KTOP];
__device__ float g_dn1[N_NODES * 2 * D_IN];  // interleaved den/num, conv1
__device__ float g_dn2[N_NODES * 2 * 64];    // interleaved den/num, conv2
__device__ float g_h1[N_NODES * 64];

__device__ unsigned g_count = 0;
__device__ unsigned g_gen = 0;

// ---------------- helpers ----------------------------------------------------
__device__ __forceinline__ void grid_sync(unsigned target) {
    __syncthreads();
    if (threadIdx.x == 0) {
        __threadfence();
        unsigned arrived = atomicAdd(&g_count, 1u);
        if (arrived == NBLK - 1) {
            g_count = 0;
            __threadfence();
            atomicAdd(&g_gen, 1u);
        } else {
            while (*((volatile unsigned*)&g_gen) < target) __nanosleep(32);
        }
        __threadfence();
    }
    __syncthreads();
}

#define QBAR(q) asm volatile("bar.sync %0, 64;" :: "r"((q) + 1) : "memory")

__device__ __forceinline__ void red_add_v4(float* addr, float a, float b, float c, float d) {
    asm volatile("red.global.add.v4.f32 [%0], {%1, %2, %3, %4};"
                 :: "l"(addr), "f"(a), "f"(b), "f"(c), "f"(d) : "memory");
}
__device__ __forceinline__ void red_add_v2(float* addr, float a, float b) {
    asm volatile("red.global.add.v2.f32 [%0], {%1, %2};"
                 :: "l"(addr), "f"(a), "f"(b) : "memory");
}

__device__ __forceinline__ unsigned long long packkey(float v, int j) {
    unsigned u = __float_as_uint(v);
    u = (u & 0x80000000u) ? ~u : (u | 0x80000000u);
    return ((unsigned long long)u << 32) | (unsigned)(1023 - j);
}
__device__ __forceinline__ unsigned long long packu(float u, int j) {
    return ((unsigned long long)__float_as_uint(u) << 32) | (unsigned)(1023 - j);
}
__device__ __forceinline__ unsigned long long wmax64(unsigned long long k) {
#pragma unroll
    for (int o = 16; o > 0; o >>= 1) {
        unsigned long long k2 = __shfl_xor_sync(0xffffffffu, k, o);
        if (k2 > k) k = k2;
    }
    return k;
}

// ---------------- shared memory union ----------------------------------------
struct alignas(16) TK {
    int dstl[LCAP]; int el[LCAP];
    float cv[LCAP];
    int   cj[LCAP + UCAP];
    int   ce[LCAP];
    unsigned msk[32];
    float attr[KTOP][ED];
    float zadd;
    int cnt, pcnt, ucnt;
    int topi8[KTOP]; int eid8[KTOP];
};
union SMem {
    TK tk[4];
    struct { float s0[4][128]; float h1s[4][256]; float hh[4][64];
             float a2[4][KTOP][ED]; int sd[4][KTOP]; int se[4][KTOP]; } c1;
    struct { float s0[4][64]; float h1s[4][128]; float h2s[4][64]; } c2;
};

// ---------------- the one kernel ----------------------------------------------
__global__ void __launch_bounds__(NT, 2)
gumbel_gcn_all(const float* __restrict__ x,
               const float* __restrict__ edge_attr,
               const float* __restrict__ gumbel,
               const float* __restrict__ mlp_w,
               const float* __restrict__ mlp_b,
               const float* __restrict__ c1_we, const float* __restrict__ c1_be,
               const float* __restrict__ c1_w1, const float* __restrict__ c1_b1,
               const float* __restrict__ c1_w2, const float* __restrict__ c1_b2,
               const float* __restrict__ c2_we, const float* __restrict__ c2_be,
               const float* __restrict__ c2_w1, const float* __restrict__ c2_b1,
               const float* __restrict__ c2_w2, const float* __restrict__ c2_b2,
               const float* __restrict__ fcw, const float* __restrict__ fcb,
               const int* __restrict__ ei, const int* __restrict__ mask,
               float* __restrict__ out) {
    __shared__ SMem sm;
    const int tid = threadIdx.x;
    const int bid = blockIdx.x;
    const int gtid = bid * NT + tid;
    const int lane = tid & 31;
    const int qid  = tid >> 6;        // 0..3
    const int qtid = tid & 63;
    const int qw   = (tid >> 5) & 1;
    const int i = bid * 4 + qid;      // P3 row (R12 map, blocks 0..255)

    unsigned base = 0;
    if (tid == 0) base = *((volatile unsigned*)&g_gen);

    // ---- prefetch gumbel row (input-only; overlaps P1 + barrier) --------------
    float4 u0, u1, u2, u3;
    if (bid < N_NODES / 4) {
        const float4* grow4 = (const float4*)(gumbel + (size_t)i * N_NODES);
        u0 = grow4[qtid];
        u1 = grow4[64 + qtid];
        u2 = grow4[128 + qtid];
        u3 = grow4[192 + qtid];
    }

    // ===== P1: block-partitioned: edges | node dots | zeroing ==================
    if (bid < 64) {
        int e = gtid;
        float acc = 0.f;
        const float4* ea = (const float4*)(edge_attr + e * ED);
#pragma unroll
        for (int q = 0; q < 4; q++) {
            float4 v = ea[q];
            acc += v.x * mlp_w[2 * D_IN + q * 4]
                 + v.y * mlp_w[2 * D_IN + q * 4 + 1]
                 + v.z * mlp_w[2 * D_IN + q * 4 + 2]
                 + v.w * mlp_w[2 * D_IN + q * 4 + 3];
        }
        g_eval[e] = acc;
        int s = ei[e];
        int d = ei[N_EDGES + e];
        int p = atomicAdd(&g_rowcnt[s], 1);
        if (p < LCAP) {
            __stcg(&g_rowdst[s * LCAP + p], d);
            __stcg(&g_rowe[s * LCAP + p], e);
        }
    } else if (bid < 192) {
        int nid = ((bid - 64) * NT + tid) >> 5;
        float p1 = 0.f, p2 = 0.f;
#pragma unroll
        for (int q = 0; q < 4; q++) {
            float xv = x[nid * D_IN + q * 32 + lane];
            p1 += xv * mlp_w[q * 32 + lane];
            p2 += xv * mlp_w[D_IN + q * 32 + lane];
        }
#pragma unroll
        for (int o = 16; o > 0; o >>= 1) {
            p1 += __shfl_down_sync(0xffffffffu, p1, o);
            p2 += __shfl_down_sync(0xffffffffu, p2, o);
        }
        if (lane == 0) { g_xwnode[nid] = p1 + mlp_b[0]; g_xwnb[nid] = p2; }
    } else {
        int zt = (bid - 192) * NT + tid;
        const float4 z4 = make_float4(0.f, 0.f, 0.f, 0.f);
        for (int idx = zt; idx < (N_NODES * 2 * D_IN) / 4; idx += 104 * NT)
            __stcg(((float4*)g_dn1) + idx, z4);
        for (int idx = zt; idx < (N_NODES * 2 * 64) / 4; idx += 104 * NT)
            __stcg(((float4*)g_dn2) + idx, z4);
    }
    grid_sync(base + 1);

    // ===== P3: topk (4 rows/block, 64 threads each, per-quarter barriers) ======
    if (bid < N_NODES / 4) {
        TK& tk = sm.tk[qid];

        int dreg = __ldcg(&g_rowdst[i * LCAP + qtid]);
        int ereg = __ldcg(&g_rowe[i * LCAP + qtid]);

        if (qtid == 0) {
            tk.pcnt = 0; tk.ucnt = 0;
            int c = __ldcg(&g_rowcnt[i]);
            __stcg(&g_rowcnt[i], 0);      // restore zero for next run
            tk.cnt = c < LCAP ? c : LCAP;
        }
        if (qtid < 32) tk.msk[qtid] = 0u;
        tk.dstl[qtid] = dreg;
        tk.el[qtid]   = ereg;
        QBAR(qid);
        int cnt = tk.cnt;

        // dedupe + primary push (last-edge-wins score, first-edge eid)
        if (qtid < cnt) {
            int d = tk.dstl[qtid], e = tk.el[qtid];
            int maxe = e, mine = e;
            for (int q = 0; q < cnt; q++) {
                if (tk.dstl[q] == d) {
                    int eq = tk.el[q];
                    maxe = max(maxe, eq); mine = min(mine, eq);
                }
            }
            atomicOr(&tk.msk[d >> 5], 1u << (d & 31));
            if (e == maxe) {
                float s = g_xwnode[i] + g_xwnb[d] + g_eval[e];
                int p = atomicAdd(&tk.pcnt, 1);
                tk.cv[p] = s; tk.cj[p] = d; tk.ce[p] = mine;
            }
        }
        QBAR(qid);
        int pcnt = tk.pcnt;

        // threshold scan on prefetched gumbel values
        {
#pragma unroll
            for (int r = 0; r < 4; r++) {
                float4 uv = (r == 0) ? u0 : (r == 1) ? u1 : (r == 2) ? u2 : u3;
                int j0 = r * 256 + qtid * 4;
                unsigned wb = tk.msk[j0 >> 5];
                int sh = j0 & 31;
                if (uv.x > UTH && !((wb >> (sh + 0)) & 1u)) { int p = atomicAdd(&tk.ucnt, 1); if (p < UCAP) tk.cj[LCAP + p] = j0; }
                if (uv.y > UTH && !((wb >> (sh + 1)) & 1u)) { int p = atomicAdd(&tk.ucnt, 1); if (p < UCAP) tk.cj[LCAP + p] = j0 + 1; }
                if (uv.z > UTH && !((wb >> (sh + 2)) & 1u)) { int p = atomicAdd(&tk.ucnt, 1); if (p < UCAP) tk.cj[LCAP + p] = j0 + 2; }
                if (uv.w > UTH && !((wb >> (sh + 3)) & 1u)) { int p = atomicAdd(&tk.ucnt, 1); if (p < UCAP) tk.cj[LCAP + p] = j0 + 3; }
            }
        }

        // sparse softmax over primaries (warp 0 of quarter)
        if (qw == 0) {
            float lm = -3.4e38f;
            for (int p = lane; p < pcnt; p += 32) lm = fmaxf(lm, tk.cv[p]);
#pragma unroll
            for (int o = 16; o > 0; o >>= 1) lm = fmaxf(lm, __shfl_xor_sync(0xffffffffu, lm, o));
            float ls = 0.f;
            for (int p = lane; p < pcnt; p += 32) ls += expf(tk.cv[p] - lm);
#pragma unroll
            for (int o = 16; o > 0; o >>= 1) ls += __shfl_xor_sync(0xffffffffu, ls, o);
            float inv = 1.f / ls;
            for (int p = lane; p < pcnt; p += 32)
                tk.cv[p] = expf(tk.cv[p] - lm) * inv;
            if (lane == 0) tk.zadd = (pcnt == 0) ? (1.f / 1024.f) : 0.f;
        }
        QBAR(qid);
        float zadd = tk.zadd;

        // rare exact fallback
        if (qw == 0 && (tk.ucnt < 8 || tk.ucnt > UCAP)) {
            if (lane == 0) tk.ucnt = 8;
            const float* grow = gumbel + (size_t)i * N_NODES;
#pragma unroll 1
            for (int r = 0; r < 8; r++) {
                unsigned long long best = 0ull;
#pragma unroll 1
                for (int q = 0; q < 32; q++) {
                    int j = q * 32 + lane;
                    if (!((tk.msk[j >> 5] >> (j & 31)) & 1u)) {
                        unsigned long long kx = packu(grow[j], j);
                        if (kx > best) best = kx;
                    }
                }
                unsigned long long m = wmax64(best);
                if (lane == 0) {
                    int j = 1023 - (int)(m & 0xFFFFFFFFull);
                    tk.cj[LCAP + r] = j;
                    tk.msk[j >> 5] |= 1u << (j & 31);
                }
                __syncwarp();
            }
        }
        QBAR(qid);

        // exact evaluation of candidates, top-8 with index tie-break
        if (qw == 0) {
            int ueff = tk.ucnt < UCAP ? tk.ucnt : UCAP;
            unsigned long long kk[4];
            int ee[4]; int jj[4];
#pragma unroll
            for (int q = 0; q < 4; q++) { kk[q] = 0ull; ee[q] = 0; jj[q] = 0; }
#pragma unroll
            for (int q = 0; q < 2; q++) {        // primaries
                int p = lane + q * 32;
                if (p < pcnt) {
                    int j = tk.cj[p];
                    float u = gumbel[(size_t)i * N_NODES + j];
                    float g = -logf(-logf(u + 1e-20f) + 1e-20f);
                    kk[q] = packkey(tk.cv[p] + zadd + g, j);
                    ee[q] = tk.ce[p]; jj[q] = j;
                }
            }
#pragma unroll
            for (int q = 0; q < 2; q++) {        // uniform candidates (z = 0)
                int p = lane + q * 32;
                if (p < ueff) {
                    int j = tk.cj[LCAP + p];
                    float u = gumbel[(size_t)i * N_NODES + j];
                    float g = -logf(-logf(u + 1e-20f) + 1e-20f);
                    kk[2 + q] = packkey(zadd + g, j);
                    ee[2 + q] = 0; jj[2 + q] = j;
                }
            }
#pragma unroll
            for (int r = 0; r < 8; r++) {
                unsigned long long best = kk[0];
#pragma unroll
                for (int q = 1; q < 4; q++) if (kk[q] > best) best = kk[q];
                unsigned long long m = wmax64(best);
#pragma unroll
                for (int q = 0; q < 4; q++) {
                    if (kk[q] == m) {
                        tk.topi8[r] = jj[q];
                        tk.eid8[r]  = ee[q];
                        g_topi[i * KTOP + r] = jj[q];
                        g_eid[i * KTOP + r]  = ee[q];
                        kk[q] = 0ull;
                    }
                }
            }
        }
        QBAR(qid);

        // conv1 edge attrs (8 selected edges)
        {
            int k0 = qtid >> 4, c0 = qtid & 15;
            tk.attr[k0][c0] = edge_attr[tk.eid8[k0] * ED + c0];
            int idx1 = qtid + 64;
            int k1 = idx1 >> 4, c1 = idx1 & 15;
            tk.attr[k1][c1] = edge_attr[tk.eid8[k1] * ED + c1];
        }
        QBAR(qid);
        {
            int f0 = qtid * 2;                       // features f0, f0+1
            float2 xv = *(const float2*)&x[i * D_IN + f0];
            float2 be = *(const float2*)&c1_be[f0];
            float2 wr[ED];
#pragma unroll
            for (int c = 0; c < ED; c++) wr[c] = *(const float2*)&c1_we[c * D_IN + f0];
#pragma unroll
            for (int kq = 0; kq < KTOP; kq++) {
                float ep0 = be.x, ep1 = be.y;
#pragma unroll
                for (int c = 0; c < ED; c++) {
                    float av = tk.attr[kq][c];
                    ep0 += av * wr[c].x;
                    ep1 += av * wr[c].y;
                }
                float m0 = fmaxf(xv.x + ep0, 0.f) + 1e-7f;
                float m1 = fmaxf(xv.y + ep1, 0.f) + 1e-7f;
                float w0 = __expf(m0);
                float w1 = __expf(m1);
                int dst = tk.topi8[kq];
                red_add_v4(&g_dn1[dst * 2 * D_IN + f0 * 2], w0, w0 * m0, w1, w1 * m1);
            }
        }
    }
    grid_sync(base + 2);

    // ===== P5: conv1 node MLP (3-4 nodes/block over all 296) + conv2 edge msgs =
    {
        const int nb   = (bid * N_NODES) / NBLK;
        const int cntn = ((bid + 1) * N_NODES) / NBLK - nb;   // 3 or 4
        for (int idx = tid; idx < 4 * 128; idx += NT) {
            int n = idx >> 7, f = idx & 127;
            float v = 0.f;
            if (n < cntn) {
                float2 dn = *(const float2*)&g_dn1[(nb + n) * 2 * D_IN + f * 2];
                v = ((dn.x > 0.f) ? dn.y / dn.x : 0.f) + x[(nb + n) * 128 + f];
            }
            sm.c1.s0[n][f] = v;
        }
        __syncthreads();
        {
            float acc[4];
            float bb = c1_b1[tid];
#pragma unroll
            for (int n = 0; n < 4; n++) acc[n] = bb;
            for (int c = 0; c < 128; c++) {
                float wv = c1_w1[c * 256 + tid];
#pragma unroll
                for (int n = 0; n < 4; n++) acc[n] += sm.c1.s0[n][c] * wv;
            }
#pragma unroll
            for (int n = 0; n < 4; n++) sm.c1.h1s[n][tid] = fmaxf(acc[n], 0.f);
        }
        __syncthreads();
        {
            int o = tid & 63, n = tid >> 6;
            float a = c1_b2[o];
            for (int c = 0; c < 256; c++) a += sm.c1.h1s[n][c] * c1_w2[c * 64 + o];
            if (n < cntn) {
                float hv = fmaxf(a, 0.f);  // post-conv relu
                g_h1[(nb + n) * 64 + o] = hv;
                sm.c1.hh[n][o] = hv;
                if (o < KTOP) {
                    sm.c1.sd[n][o] = g_topi[(nb + n) * KTOP + o];
                    sm.c1.se[n][o] = g_eid[(nb + n) * KTOP + o];
                }
            }
        }
        __syncthreads();
        for (int idx = tid; idx < 4 * KTOP * ED; idx += NT) {
            int n = idx >> 7, r = idx & 127;
            if (n < cntn) {
                int kq = r >> 4, c = r & 15;
                sm.c1.a2[n][kq][c] = edge_attr[sm.c1.se[n][kq] * ED + c];
            }
        }
        __syncthreads();
        {
            int f = tid & 63, n = tid >> 6;
            if (n < cntn) {
                float xv = sm.c1.hh[n][f];
                float beh = c2_be[f];
                float wr[ED];
#pragma unroll
                for (int c = 0; c < ED; c++) wr[c] = c2_we[c * 64 + f];
#pragma unroll
                for (int kq = 0; kq < KTOP; kq++) {
                    float ep = beh;
#pragma unroll
                    for (int c = 0; c < ED; c++) ep += sm.c1.a2[n][kq][c] * wr[c];
                    float m = fmaxf(xv + ep, 0.f) + 1e-7f;
                    float wgt = __expf(m);
                    int dst = sm.c1.sd[n][kq];
                    red_add_v2(&g_dn2[dst * 128 + f * 2], wgt, wgt * m);
                }
            }
        }
    }
    grid_sync(base + 3);

    // ===== P7: conv2 node MLP + final FC + mask (3-4 nodes/block) ==============
    {
        const int nb   = (bid * N_NODES) / NBLK;
        const int cntn = ((bid + 1) * N_NODES) / NBLK - nb;
        for (int idx = tid; idx < 4 * 64; idx += NT) {
            int n = idx >> 6, f = idx & 63;
            float v = 0.f;
            if (n < cntn) {
                float2 dn = *(const float2*)&g_dn2[(nb + n) * 128 + f * 2];
                v = ((dn.x > 0.f) ? dn.y / dn.x : 0.f) + g_h1[(nb + n) * 64 + f];
            }
            sm.c2.s0[n][f] = v;
        }
        __syncthreads();
        {
            int h = tid & 127, n2 = (tid >> 7) * 2;
            float a0 = c2_b1[h], a1 = a0;
            for (int c = 0; c < 64; c++) {
                float wv = c2_w1[c * 128 + h];
                a0 += sm.c2.s0[n2][c] * wv;
                a1 += sm.c2.s0[n2 + 1][c] * wv;
            }
            sm.c2.h1s[n2][h]     = fmaxf(a0, 0.f);
            sm.c2.h1s[n2 + 1][h] = fmaxf(a1, 0.f);
        }
        __syncthreads();
        {
            int o = tid & 63, n = tid >> 6;
            float a = c2_b2[o];
            for (int c = 0; c < 128; c++) a += sm.c2.h1s[n][c] * c2_w2[c * 64 + o];
            sm.c2.h2s[n][o] = fmaxf(a, 0.f);  // post-conv relu (garbage if n>=cntn, unused)
        }
        __syncthreads();
        for (int idx = tid; idx < 4 * 40; idx += NT) {
            int n = idx / 40, o2 = idx % 40;
            if (n < cntn) {
                float a2 = fcb[o2];
#pragma unroll 16
                for (int c = 0; c < 64; c++) a2 += sm.c2.h2s[n][c] * fcw[c * 40 + o2];
                out[(nb + n) * 40 + o2] = (mask[nb + n] != 0) ? a2 : 0.f;
            }
        }
    }
}

// ---------------- launch ------------------------------------------------------
extern "C" void kernel_launch(void* const* d_in, const int* in_sizes, int n_in,
                              void* d_out, int out_size) {
    gumbel_gcn_all<<<NBLK, NT>>>(
        (const float*)d_in[0],  (const float*)d_in[1],  (const float*)d_in[2],
        (const float*)d_in[3],  (const float*)d_in[4],
        (const float*)d_in[5],  (const float*)d_in[6],
        (const float*)d_in[7],  (const float*)d_in[8],
        (const float*)d_in[9],  (const float*)d_in[10],
        (const float*)d_in[11], (const float*)d_in[12],
        (const float*)d_in[13], (const float*)d_in[14],
        (const float*)d_in[15], (const float*)d_in[16],
        (const float*)d_in[17], (const float*)d_in[18],
        (const int*)d_in[20],   (const int*)d_in[21],
        (float*)d_out);
}